// round 2
// baseline (speedup 1.0000x reference)
#include <cuda_runtime.h>
#include <cstdint>

// ---------------------------------------------------------------------------
// Problem constants: B=256, T=512, I=64, H=256, 2-layer bidirectional LSTM,
// FC head on last timestep. Key optimization: layer-1 reverse direction only
// contributes h at t=T-1, which is its FIRST scan step from zero state ->
// full reverse recurrence + full reverse input projection are skipped.
// ---------------------------------------------------------------------------

#define NCTA 128

// Scratch (device globals; no cudaMalloc allowed)
__device__ float g_xT  [512 * 64 * 256];        // x transposed -> [t][k][b]
__device__ float g_xp0f[512 * 1024 * 256];      // layer0 fwd input proj [t][4H][b]
__device__ float g_xp0r[512 * 1024 * 256];      // layer0 rev input proj
__device__ float g_h0c [512 * 512 * 256];       // layer0 output concat [t][2H][b]
__device__ float g_xp1f[512 * 1024 * 256];      // layer1 fwd input proj
__device__ float g_xp1r[1024 * 256];            // layer1 rev input proj @ t=T-1 only
__device__ float g_h1  [512 * 256 * 256];       // layer1 fwd hidden [t][H][b]

__device__ unsigned g_cnt = 0;
__device__ unsigned g_gen = 0;

__device__ __forceinline__ float sigm(float x) { return 1.0f / (1.0f + __expf(-x)); }

__device__ __forceinline__ void grid_barrier() {
    __syncthreads();
    if (threadIdx.x == 0) {
        __threadfence();
        unsigned gen = *((volatile unsigned*)&g_gen);   // snapshot BEFORE arriving
        if (atomicAdd(&g_cnt, 1u) == NCTA - 1) {
            atomicExch(&g_cnt, 0u);
            __threadfence();
            atomicAdd(&g_gen, 1u);
        } else {
            while (*((volatile unsigned*)&g_gen) == gen) __nanosleep(64);
        }
    }
    __syncthreads();
}

// ---------------------------------------------------------------------------
// Transpose x[b][t*64+k] -> xT[(t*64+k)][b]   (256 x 32768 transpose)
// ---------------------------------------------------------------------------
__global__ void transpose_x(const float* __restrict__ x, float* __restrict__ xT) {
    __shared__ float tile[32][33];
    int c0 = blockIdx.x * 32, r0 = blockIdx.y * 32;
    int tx = threadIdx.x, ty = threadIdx.y;
#pragma unroll
    for (int i = 0; i < 32; i += 8)
        tile[ty + i][tx] = x[(size_t)(r0 + ty + i) * 32768 + c0 + tx];
    __syncthreads();
#pragma unroll
    for (int i = 0; i < 32; i += 8)
        xT[(size_t)(c0 + ty + i) * 256 + r0 + tx] = tile[tx][ty + i];
}

// ---------------------------------------------------------------------------
// GEMM: C[t][n][m] = sum_k A[t][k][m] * W[n][k] + b1[n] + b2[n]
// M = 256 fixed. grid = (T, M/128, N/128), block = 256, 8x8 microtiles.
// ---------------------------------------------------------------------------
__global__ void gemm_tn(const float* __restrict__ A, const float* __restrict__ W,
                        const float* __restrict__ b1, const float* __restrict__ b2,
                        float* __restrict__ C, int K, int N) {
    __shared__ float As[16][128];
    __shared__ float Ws[16][128];
    int t  = blockIdx.x;
    int m0 = blockIdx.y * 128, n0 = blockIdx.z * 128;
    const float* At = A + (size_t)t * K * 256;
    float* Ct = C + (size_t)t * N * 256;
    int tid = threadIdx.x;
    int mo = (tid & 15) * 8, no = (tid >> 4) * 8;
    int nn = tid >> 1, half = tid & 1;

    float acc[8][8];   // [ni][mi]
#pragma unroll
    for (int i = 0; i < 8; i++)
#pragma unroll
        for (int jj = 0; jj < 8; jj++) acc[i][jj] = 0.0f;

    for (int k0 = 0; k0 < K; k0 += 16) {
#pragma unroll
        for (int q = 0; q < 2; q++) {
            int f4 = tid + 256 * q;
            int kk = f4 >> 5, m4 = f4 & 31;
            *(float4*)&As[kk][m4 * 4] =
                *(const float4*)&At[(size_t)(k0 + kk) * 256 + m0 + m4 * 4];
        }
        {
            const float* wp = W + (size_t)(n0 + nn) * K + k0 + half * 8;
            float4 wa = *(const float4*)wp;
            float4 wb = *(const float4*)(wp + 4);
            int kb = half * 8;
            Ws[kb + 0][nn] = wa.x; Ws[kb + 1][nn] = wa.y;
            Ws[kb + 2][nn] = wa.z; Ws[kb + 3][nn] = wa.w;
            Ws[kb + 4][nn] = wb.x; Ws[kb + 5][nn] = wb.y;
            Ws[kb + 6][nn] = wb.z; Ws[kb + 7][nn] = wb.w;
        }
        __syncthreads();
#pragma unroll
        for (int kk = 0; kk < 16; kk++) {
            float4 a0 = *(float4*)&As[kk][mo];
            float4 a1 = *(float4*)&As[kk][mo + 4];
            float4 w0 = *(float4*)&Ws[kk][no];
            float4 w1 = *(float4*)&Ws[kk][no + 4];
            float am[8] = {a0.x, a0.y, a0.z, a0.w, a1.x, a1.y, a1.z, a1.w};
            float wn[8] = {w0.x, w0.y, w0.z, w0.w, w1.x, w1.y, w1.z, w1.w};
#pragma unroll
            for (int ni = 0; ni < 8; ni++)
#pragma unroll
                for (int mi = 0; mi < 8; mi++)
                    acc[ni][mi] += wn[ni] * am[mi];
        }
        __syncthreads();
    }
#pragma unroll
    for (int ni = 0; ni < 8; ni++) {
        int n = n0 + no + ni;
        float bias = b1[n] + b2[n];
        float4 v0 = make_float4(acc[ni][0] + bias, acc[ni][1] + bias,
                                acc[ni][2] + bias, acc[ni][3] + bias);
        float4 v1 = make_float4(acc[ni][4] + bias, acc[ni][5] + bias,
                                acc[ni][6] + bias, acc[ni][7] + bias);
        *(float4*)&Ct[(size_t)n * 256 + m0 + mo]     = v0;
        *(float4*)&Ct[(size_t)n * 256 + m0 + mo + 4] = v1;
    }
}

// ---------------------------------------------------------------------------
// Persistent recurrent kernel. 128 CTAs, 256 thr, one grid barrier per step.
// Each CTA owns UNITS hidden units (=4*UNITS gate columns) for one direction.
// Weights for its columns stay in shared for all 512 steps; c stays in regs.
// h written to hout[t][HOUT_ROWS][256] (t-indexed => natural ping-pong).
// ---------------------------------------------------------------------------
template <int UNITS, int NDIR>
__global__ void lstm_rec(const float* __restrict__ xp_f, const float* __restrict__ xp_r,
                         const float* __restrict__ whh_f, const float* __restrict__ whh_r,
                         float* __restrict__ hout) {
    constexpr int COLS = 4 * UNITS;
    constexpr int CG   = COLS / 4;
    constexpr int BG   = 256 / CG;
    constexpr int TB   = 256 / BG;        // batches per thread in GEMM tile
    constexpr int HOUT_ROWS = NDIR * 256;
    constexpr int CPD  = NCTA / NDIR;     // CTAs per direction
    constexpr int BPU  = 256 / UNITS;     // threads per owned unit

    extern __shared__ float sm[];
    float* hsh = sm;                        // [32][256]
    float* wsh = sm + 32 * 256;             // [256][COLS]
    float* gsh = wsh + 256 * COLS;          // [COLS][256]

    int tid = threadIdx.x;
    int dir = blockIdx.x / CPD;
    int cg  = blockIdx.x % CPD;
    int u0  = cg * UNITS;
    int dirbase = dir * 256;
    const float* xp  = dir ? xp_r : xp_f;
    const float* whh = dir ? whh_r : whh_f;

    // load w_hh slice: wsh[k][c], local col c = gate*UNITS + j
    for (int idx = tid; idx < COLS * 256; idx += 256) {
        int c = idx / 256, k = idx % 256;
        int row = (c / UNITS) * 256 + u0 + (c % UNITS);
        wsh[k * COLS + c] = whh[(size_t)row * 256 + k];
    }

    int bgrp = tid % BG, cgrp = tid / BG;
    int bbase = bgrp * TB, cbase = cgrp * 4;

    int j  = tid / BPU;               // owned unit (local)
    int sb = (tid % BPU) * UNITS;     // owned batch start
    float creg[UNITS];
#pragma unroll
    for (int m = 0; m < UNITS; m++) creg[m] = 0.0f;

    int rowc[4];
#pragma unroll
    for (int ci = 0; ci < 4; ci++) {
        int c = cbase + ci;
        rowc[ci] = (c / UNITS) * 256 + u0 + (c % UNITS);
    }
    __syncthreads();

    for (int s = 0; s < 512; s++) {
        int t = dir ? (511 - s) : s;
        float acc[4][TB];
        const float* xpt = xp + (size_t)t * 1024 * 256;
#pragma unroll
        for (int ci = 0; ci < 4; ci++) {
            if constexpr (TB == 4) {
                float4 v = *(const float4*)&xpt[(size_t)rowc[ci] * 256 + bbase];
                acc[ci][0] = v.x; acc[ci][1] = v.y; acc[ci][2] = v.z; acc[ci][3] = v.w;
            } else {
                float2 v = *(const float2*)&xpt[(size_t)rowc[ci] * 256 + bbase];
                acc[ci][0] = v.x; acc[ci][1] = v.y;
            }
        }
        if (s > 0) {
            int tp = dir ? (t + 1) : (t - 1);
            const float* hprev = hout + ((size_t)tp * HOUT_ROWS + dirbase) * 256;
            for (int kb = 0; kb < 8; kb++) {
                __syncthreads();
#pragma unroll
                for (int q = 0; q < 8; q++) {
                    int f4 = tid + 256 * q;
                    int kk = f4 >> 6, b4 = f4 & 63;
                    *(float4*)&hsh[kk * 256 + b4 * 4] =
                        *(const float4*)&hprev[(size_t)(kb * 32 + kk) * 256 + b4 * 4];
                }
                __syncthreads();
#pragma unroll
                for (int kk = 0; kk < 32; kk++) {
                    float hv[TB];
                    if constexpr (TB == 4) {
                        float4 v = *(float4*)&hsh[kk * 256 + bbase];
                        hv[0] = v.x; hv[1] = v.y; hv[2] = v.z; hv[3] = v.w;
                    } else {
                        float2 v = *(float2*)&hsh[kk * 256 + bbase];
                        hv[0] = v.x; hv[1] = v.y;
                    }
                    float4 wv = *(float4*)&wsh[(kb * 32 + kk) * COLS + cbase];
                    float wn[4] = {wv.x, wv.y, wv.z, wv.w};
#pragma unroll
                    for (int ci = 0; ci < 4; ci++)
#pragma unroll
                        for (int bi = 0; bi < TB; bi++)
                            acc[ci][bi] += wn[ci] * hv[bi];
                }
            }
        }
        // exchange gates through shared so each thread can update its units
        __syncthreads();
#pragma unroll
        for (int ci = 0; ci < 4; ci++) {
            if constexpr (TB == 4) {
                *(float4*)&gsh[(cbase + ci) * 256 + bbase] =
                    make_float4(acc[ci][0], acc[ci][1], acc[ci][2], acc[ci][3]);
            } else {
                *(float2*)&gsh[(cbase + ci) * 256 + bbase] =
                    make_float2(acc[ci][0], acc[ci][1]);
            }
        }
        __syncthreads();
        float hv[UNITS];
#pragma unroll
        for (int m = 0; m < UNITS; m++) {
            int b = sb + m;
            float ig = gsh[(0 * UNITS + j) * 256 + b];
            float fg = gsh[(1 * UNITS + j) * 256 + b];
            float gg = gsh[(2 * UNITS + j) * 256 + b];
            float og = gsh[(3 * UNITS + j) * 256 + b];
            float cc = sigm(fg) * creg[m] + sigm(ig) * tanhf(gg);
            creg[m] = cc;
            hv[m] = sigm(og) * tanhf(cc);
        }
        float* hw = hout + ((size_t)t * HOUT_ROWS + dirbase + u0 + j) * 256 + sb;
        if constexpr (UNITS == 4)
            *(float4*)hw = make_float4(hv[0], hv[1], hv[2], hv[3]);
        else
            *(float2*)hw = make_float2(hv[0], hv[1]);
        grid_barrier();
    }
}

// ---------------------------------------------------------------------------
// Finalize: layer-1 reverse single step from zero state + FC head.
// ---------------------------------------------------------------------------
__global__ void finalize_kernel(const float* __restrict__ xp1r,
                                const float* __restrict__ h1last,
                                const float* __restrict__ fc_w,
                                const float* __restrict__ fc_b,
                                float* __restrict__ out) {
    int b = blockIdx.x, u = threadIdx.x;
    float ig = xp1r[(size_t)(0   + u) * 256 + b];
    float gg = xp1r[(size_t)(512 + u) * 256 + b];
    float og = xp1r[(size_t)(768 + u) * 256 + b];
    float cc = sigm(ig) * tanhf(gg);          // sigmoid(f)*c0 == 0
    float hr = sigm(og) * tanhf(cc);
    float p = fc_w[u] * h1last[(size_t)u * 256 + b] + fc_w[256 + u] * hr;
    __shared__ float red[256];
    red[u] = p;
    __syncthreads();
    for (int off = 128; off > 0; off >>= 1) {
        if (u < off) red[u] += red[u + off];
        __syncthreads();
    }
    if (u == 0) out[b] = red[0] + fc_b[0];
}

// ---------------------------------------------------------------------------
extern "C" void kernel_launch(void* const* d_in, const int* in_sizes, int n_in,
                              void* d_out, int out_size) {
    const float* x        = (const float*)d_in[0];
    const float* w_ih_l0  = (const float*)d_in[1];
    const float* w_hh_l0  = (const float*)d_in[2];
    const float* b_ih_l0  = (const float*)d_in[3];
    const float* b_hh_l0  = (const float*)d_in[4];
    const float* w_ih_l0r = (const float*)d_in[5];
    const float* w_hh_l0r = (const float*)d_in[6];
    const float* b_ih_l0r = (const float*)d_in[7];
    const float* b_hh_l0r = (const float*)d_in[8];
    const float* w_ih_l1  = (const float*)d_in[9];
    const float* w_hh_l1  = (const float*)d_in[10];
    const float* b_ih_l1  = (const float*)d_in[11];
    const float* b_hh_l1  = (const float*)d_in[12];
    const float* w_ih_l1r = (const float*)d_in[13];
    const float* b_ih_l1r = (const float*)d_in[15];
    const float* b_hh_l1r = (const float*)d_in[16];
    const float* fc_w     = (const float*)d_in[17];
    const float* fc_b     = (const float*)d_in[18];
    float* out = (float*)d_out;
    (void)in_sizes; (void)n_in; (void)out_size;

    float *xT, *xp0f, *xp0r, *h0c, *xp1f, *xp1r, *h1;
    cudaGetSymbolAddress((void**)&xT,   g_xT);
    cudaGetSymbolAddress((void**)&xp0f, g_xp0f);
    cudaGetSymbolAddress((void**)&xp0r, g_xp0r);
    cudaGetSymbolAddress((void**)&h0c,  g_h0c);
    cudaGetSymbolAddress((void**)&xp1f, g_xp1f);
    cudaGetSymbolAddress((void**)&xp1r, g_xp1r);
    cudaGetSymbolAddress((void**)&h1,   g_h1);

    cudaFuncSetAttribute((const void*)lstm_rec<4, 2>,
                         cudaFuncAttributeMaxDynamicSharedMemorySize, 65536);
    cudaFuncSetAttribute((const void*)lstm_rec<2, 1>,
                         cudaFuncAttributeMaxDynamicSharedMemorySize, 49152);

    // x -> xT [t][k][b]
    transpose_x<<<dim3(1024, 8), dim3(32, 8)>>>(x, xT);
    // layer-0 input projections (both directions)
    gemm_tn<<<dim3(512, 2, 8), 256>>>(xT, w_ih_l0,  b_ih_l0,  b_hh_l0,  xp0f, 64, 1024);
    gemm_tn<<<dim3(512, 2, 8), 256>>>(xT, w_ih_l0r, b_ih_l0r, b_hh_l0r, xp0r, 64, 1024);
    // layer-0 recurrence (fwd + rev concurrently)
    lstm_rec<4, 2><<<128, 256, 65536>>>(xp0f, xp0r, w_hh_l0, w_hh_l0r, h0c);
    // layer-1 fwd input projection (full) + rev projection at t=T-1 only
    gemm_tn<<<dim3(512, 2, 8), 256>>>(h0c, w_ih_l1, b_ih_l1, b_hh_l1, xp1f, 512, 1024);
    gemm_tn<<<dim3(1, 2, 8), 256>>>(h0c + (size_t)511 * 512 * 256,
                                    w_ih_l1r, b_ih_l1r, b_hh_l1r, xp1r, 512, 1024);
    // layer-1 fwd recurrence
    lstm_rec<2, 1><<<128, 256, 49152>>>(xp1f, xp1f, w_hh_l1, w_hh_l1, h1);
    // layer-1 rev single step + FC head
    finalize_kernel<<<256, 256>>>(xp1r, h1 + (size_t)511 * 256 * 256, fc_w, fc_b, out);
}

// round 3
// speedup vs baseline: 1.1007x; 1.1007x over previous
#include <cuda_runtime.h>
#include <cstdint>

// ---------------------------------------------------------------------------
// B=256, T=512, I=64, H=256, 2-layer bidirectional LSTM, FC on last timestep.
// Layer-1 reverse collapses to a single closed-form step (h0=0 at t=T-1).
// Round 3: input-projection GEMMs moved to TF32 tensor cores (mma.sync m16n8k8).
// ---------------------------------------------------------------------------

#define NCTA 128

__device__ float g_xT  [512 * 64 * 256];        // x transposed -> [t][k][b]
__device__ float g_xp0f[512 * 1024 * 256];      // layer0 fwd input proj [t][4H][b]
__device__ float g_xp0r[512 * 1024 * 256];      // layer0 rev input proj
__device__ float g_h0c [512 * 512 * 256];       // layer0 output concat [t][2H][b]
__device__ float g_xp1f[512 * 1024 * 256];      // layer1 fwd input proj
__device__ float g_xp1r[1024 * 256];            // layer1 rev input proj @ t=T-1
__device__ float g_h1  [512 * 256 * 256];       // layer1 fwd hidden [t][H][b]

__device__ unsigned g_cnt = 0;
__device__ unsigned g_gen = 0;

__device__ __forceinline__ float sigm(float x) { return 1.0f / (1.0f + __expf(-x)); }

__device__ __forceinline__ uint32_t f2tf32(float x) {
    uint32_t r;
    asm("cvt.rna.tf32.f32 %0, %1;" : "=r"(r) : "f"(x));
    return r;
}

__device__ __forceinline__ void mma_tf32(float c[4], const uint32_t a[4], const uint32_t b[2]) {
    asm volatile(
        "mma.sync.aligned.m16n8k8.row.col.f32.tf32.tf32.f32 "
        "{%0,%1,%2,%3}, {%4,%5,%6,%7}, {%8,%9}, {%0,%1,%2,%3};"
        : "+f"(c[0]), "+f"(c[1]), "+f"(c[2]), "+f"(c[3])
        : "r"(a[0]), "r"(a[1]), "r"(a[2]), "r"(a[3]), "r"(b[0]), "r"(b[1]));
}

__device__ __forceinline__ void grid_barrier() {
    __syncthreads();
    if (threadIdx.x == 0) {
        __threadfence();
        unsigned gen = *((volatile unsigned*)&g_gen);
        if (atomicAdd(&g_cnt, 1u) == NCTA - 1) {
            atomicExch(&g_cnt, 0u);
            __threadfence();
            atomicAdd(&g_gen, 1u);
        } else {
            while (*((volatile unsigned*)&g_gen) == gen) __nanosleep(64);
        }
    }
    __syncthreads();
}

// ---------------------------------------------------------------------------
// Transpose x[b][t*64+k] -> xT[(t*64+k)][b]
// ---------------------------------------------------------------------------
__global__ void transpose_x(const float* __restrict__ x, float* __restrict__ xT) {
    __shared__ float tile[32][33];
    int c0 = blockIdx.x * 32, r0 = blockIdx.y * 32;
    int tx = threadIdx.x, ty = threadIdx.y;
#pragma unroll
    for (int i = 0; i < 32; i += 8)
        tile[ty + i][tx] = x[(size_t)(r0 + ty + i) * 32768 + c0 + tx];
    __syncthreads();
#pragma unroll
    for (int i = 0; i < 32; i += 8)
        xT[(size_t)(c0 + ty + i) * 256 + r0 + tx] = tile[tx][ty + i];
}

// ---------------------------------------------------------------------------
// TF32 tensor-core GEMM: C[t][n][m] = sum_k W[n][k]*A[t][k][m] + b1[n] + b2[n]
// grid = (T, M/128, N/128), block = 256 (8 warps; warp tile 64n x 32m).
// mma.m16n8k8: "M"=n rows, "N"=batch cols, "K"=k.
// ---------------------------------------------------------------------------
#define WS_STRIDE 20   // Ws[n][k], padded: conflict-free for a-frag reads
#define AS_STRIDE 132  // As[k][b], padded: conflict-free for b-frag reads

__global__ void gemm_tf32(const float* __restrict__ A, const float* __restrict__ W,
                          const float* __restrict__ b1, const float* __restrict__ b2,
                          float* __restrict__ C, int K, int N) {
    __shared__ uint32_t Ws[128 * WS_STRIDE];
    __shared__ uint32_t As[16 * AS_STRIDE];

    int t  = blockIdx.x;
    int m0 = blockIdx.y * 128, n0 = blockIdx.z * 128;
    const float* At = A + (size_t)t * K * 256 + m0;
    const float* Wt = W + (size_t)n0 * K;
    float* Ct = C + (size_t)t * N * 256;

    int tid = threadIdx.x;
    int warp = tid >> 5, lane = tid & 31;
    int wn = (warp >> 2) * 64;   // warp n-origin (0 or 64)
    int wb = (warp & 3) * 32;    // warp batch-origin (0,32,64,96)
    int lr = lane >> 2, lc = lane & 3;

    float acc[4][4][4];
#pragma unroll
    for (int i = 0; i < 4; i++)
#pragma unroll
        for (int jj = 0; jj < 4; jj++)
#pragma unroll
            for (int r = 0; r < 4; r++) acc[i][jj][r] = 0.0f;

    for (int k0 = 0; k0 < K; k0 += 16) {
        // stage A[k0..+16][m0..+128] -> As (convert to tf32)
#pragma unroll
        for (int q = 0; q < 2; q++) {
            int f = tid + 256 * q;
            int kk = f >> 5, b4 = (f & 31) * 4;
            float4 v = *(const float4*)&At[(size_t)(k0 + kk) * 256 + b4];
            uint4 u = make_uint4(f2tf32(v.x), f2tf32(v.y), f2tf32(v.z), f2tf32(v.w));
            *(uint4*)&As[kk * AS_STRIDE + b4] = u;
        }
        // stage W[n0..+128][k0..+16] -> Ws (convert to tf32)
#pragma unroll
        for (int q = 0; q < 2; q++) {
            int f = tid + 256 * q;
            int n = f >> 2, kq = (f & 3) * 4;
            float4 v = *(const float4*)&Wt[(size_t)n * K + k0 + kq];
            uint4 u = make_uint4(f2tf32(v.x), f2tf32(v.y), f2tf32(v.z), f2tf32(v.w));
            *(uint4*)&Ws[n * WS_STRIDE + kq] = u;
        }
        __syncthreads();

#pragma unroll
        for (int ks = 0; ks < 2; ks++) {
            int kk = ks * 8;
            uint32_t a[4][4], b[4][2];
#pragma unroll
            for (int ni = 0; ni < 4; ni++) {
                int n = wn + ni * 16 + lr;
                a[ni][0] = Ws[n * WS_STRIDE + kk + lc];
                a[ni][1] = Ws[(n + 8) * WS_STRIDE + kk + lc];
                a[ni][2] = Ws[n * WS_STRIDE + kk + lc + 4];
                a[ni][3] = Ws[(n + 8) * WS_STRIDE + kk + lc + 4];
            }
#pragma unroll
            for (int bi = 0; bi < 4; bi++) {
                int bb = wb + bi * 8 + lr;
                b[bi][0] = As[(kk + lc) * AS_STRIDE + bb];
                b[bi][1] = As[(kk + lc + 4) * AS_STRIDE + bb];
            }
#pragma unroll
            for (int ni = 0; ni < 4; ni++)
#pragma unroll
                for (int bi = 0; bi < 4; bi++)
                    mma_tf32(acc[ni][bi], a[ni], b[bi]);
        }
        __syncthreads();
    }

    // epilogue: add bias, write float2 per (ni, half, bi)
#pragma unroll
    for (int ni = 0; ni < 4; ni++) {
#pragma unroll
        for (int h = 0; h < 2; h++) {
            int n = n0 + wn + ni * 16 + lr + h * 8;
            float bias = b1[n] + b2[n];
#pragma unroll
            for (int bi = 0; bi < 4; bi++) {
                int bb = m0 + wb + bi * 8 + lc * 2;
                float2 v = make_float2(acc[ni][bi][h * 2] + bias,
                                       acc[ni][bi][h * 2 + 1] + bias);
                *(float2*)&Ct[(size_t)n * 256 + bb] = v;
            }
        }
    }
}

// ---------------------------------------------------------------------------
// Persistent recurrent kernel (unchanged from R2). 128 CTAs, 256 thr,
// one grid barrier per step. Each CTA owns UNITS hidden units per direction.
// ---------------------------------------------------------------------------
template <int UNITS, int NDIR>
__global__ void lstm_rec(const float* __restrict__ xp_f, const float* __restrict__ xp_r,
                         const float* __restrict__ whh_f, const float* __restrict__ whh_r,
                         float* __restrict__ hout) {
    constexpr int COLS = 4 * UNITS;
    constexpr int CG   = COLS / 4;
    constexpr int BG   = 256 / CG;
    constexpr int TB   = 256 / BG;
    constexpr int HOUT_ROWS = NDIR * 256;
    constexpr int CPD  = NCTA / NDIR;
    constexpr int BPU  = 256 / UNITS;

    extern __shared__ float sm[];
    float* hsh = sm;
    float* wsh = sm + 32 * 256;
    float* gsh = wsh + 256 * COLS;

    int tid = threadIdx.x;
    int dir = blockIdx.x / CPD;
    int cg  = blockIdx.x % CPD;
    int u0  = cg * UNITS;
    int dirbase = dir * 256;
    const float* xp  = dir ? xp_r : xp_f;
    const float* whh = dir ? whh_r : whh_f;

    for (int idx = tid; idx < COLS * 256; idx += 256) {
        int c = idx / 256, k = idx % 256;
        int row = (c / UNITS) * 256 + u0 + (c % UNITS);
        wsh[k * COLS + c] = whh[(size_t)row * 256 + k];
    }

    int bgrp = tid % BG, cgrp = tid / BG;
    int bbase = bgrp * TB, cbase = cgrp * 4;

    int j  = tid / BPU;
    int sb = (tid % BPU) * UNITS;
    float creg[UNITS];
#pragma unroll
    for (int m = 0; m < UNITS; m++) creg[m] = 0.0f;

    int rowc[4];
#pragma unroll
    for (int ci = 0; ci < 4; ci++) {
        int c = cbase + ci;
        rowc[ci] = (c / UNITS) * 256 + u0 + (c % UNITS);
    }
    __syncthreads();

    for (int s = 0; s < 512; s++) {
        int t = dir ? (511 - s) : s;
        float acc[4][TB];
        const float* xpt = xp + (size_t)t * 1024 * 256;
#pragma unroll
        for (int ci = 0; ci < 4; ci++) {
            if constexpr (TB == 4) {
                float4 v = *(const float4*)&xpt[(size_t)rowc[ci] * 256 + bbase];
                acc[ci][0] = v.x; acc[ci][1] = v.y; acc[ci][2] = v.z; acc[ci][3] = v.w;
            } else {
                float2 v = *(const float2*)&xpt[(size_t)rowc[ci] * 256 + bbase];
                acc[ci][0] = v.x; acc[ci][1] = v.y;
            }
        }
        if (s > 0) {
            int tp = dir ? (t + 1) : (t - 1);
            const float* hprev = hout + ((size_t)tp * HOUT_ROWS + dirbase) * 256;
            for (int kb = 0; kb < 8; kb++) {
                __syncthreads();
#pragma unroll
                for (int q = 0; q < 8; q++) {
                    int f4 = tid + 256 * q;
                    int kk = f4 >> 6, b4 = f4 & 63;
                    *(float4*)&hsh[kk * 256 + b4 * 4] =
                        *(const float4*)&hprev[(size_t)(kb * 32 + kk) * 256 + b4 * 4];
                }
                __syncthreads();
#pragma unroll
                for (int kk = 0; kk < 32; kk++) {
                    float hv[TB];
                    if constexpr (TB == 4) {
                        float4 v = *(float4*)&hsh[kk * 256 + bbase];
                        hv[0] = v.x; hv[1] = v.y; hv[2] = v.z; hv[3] = v.w;
                    } else {
                        float2 v = *(float2*)&hsh[kk * 256 + bbase];
                        hv[0] = v.x; hv[1] = v.y;
                    }
                    float4 wv = *(float4*)&wsh[(kb * 32 + kk) * COLS + cbase];
                    float wn[4] = {wv.x, wv.y, wv.z, wv.w};
#pragma unroll
                    for (int ci = 0; ci < 4; ci++)
#pragma unroll
                        for (int bi = 0; bi < TB; bi++)
                            acc[ci][bi] += wn[ci] * hv[bi];
                }
            }
        }
        __syncthreads();
#pragma unroll
        for (int ci = 0; ci < 4; ci++) {
            if constexpr (TB == 4) {
                *(float4*)&gsh[(cbase + ci) * 256 + bbase] =
                    make_float4(acc[ci][0], acc[ci][1], acc[ci][2], acc[ci][3]);
            } else {
                *(float2*)&gsh[(cbase + ci) * 256 + bbase] =
                    make_float2(acc[ci][0], acc[ci][1]);
            }
        }
        __syncthreads();
        float hv[UNITS];
#pragma unroll
        for (int m = 0; m < UNITS; m++) {
            int b = sb + m;
            float ig = gsh[(0 * UNITS + j) * 256 + b];
            float fg = gsh[(1 * UNITS + j) * 256 + b];
            float gg = gsh[(2 * UNITS + j) * 256 + b];
            float og = gsh[(3 * UNITS + j) * 256 + b];
            float cc = sigm(fg) * creg[m] + sigm(ig) * tanhf(gg);
            creg[m] = cc;
            hv[m] = sigm(og) * tanhf(cc);
        }
        float* hw = hout + ((size_t)t * HOUT_ROWS + dirbase + u0 + j) * 256 + sb;
        if constexpr (UNITS == 4)
            *(float4*)hw = make_float4(hv[0], hv[1], hv[2], hv[3]);
        else
            *(float2*)hw = make_float2(hv[0], hv[1]);
        grid_barrier();
    }
}

// ---------------------------------------------------------------------------
// Finalize: layer-1 reverse single step from zero state + FC head.
// ---------------------------------------------------------------------------
__global__ void finalize_kernel(const float* __restrict__ xp1r,
                                const float* __restrict__ h1last,
                                const float* __restrict__ fc_w,
                                const float* __restrict__ fc_b,
                                float* __restrict__ out) {
    int b = blockIdx.x, u = threadIdx.x;
    float ig = xp1r[(size_t)(0   + u) * 256 + b];
    float gg = xp1r[(size_t)(512 + u) * 256 + b];
    float og = xp1r[(size_t)(768 + u) * 256 + b];
    float cc = sigm(ig) * tanhf(gg);
    float hr = sigm(og) * tanhf(cc);
    float p = fc_w[u] * h1last[(size_t)u * 256 + b] + fc_w[256 + u] * hr;
    __shared__ float red[256];
    red[u] = p;
    __syncthreads();
    for (int off = 128; off > 0; off >>= 1) {
        if (u < off) red[u] += red[u + off];
        __syncthreads();
    }
    if (u == 0) out[b] = red[0] + fc_b[0];
}

// ---------------------------------------------------------------------------
extern "C" void kernel_launch(void* const* d_in, const int* in_sizes, int n_in,
                              void* d_out, int out_size) {
    const float* x        = (const float*)d_in[0];
    const float* w_ih_l0  = (const float*)d_in[1];
    const float* w_hh_l0  = (const float*)d_in[2];
    const float* b_ih_l0  = (const float*)d_in[3];
    const float* b_hh_l0  = (const float*)d_in[4];
    const float* w_ih_l0r = (const float*)d_in[5];
    const float* w_hh_l0r = (const float*)d_in[6];
    const float* b_ih_l0r = (const float*)d_in[7];
    const float* b_hh_l0r = (const float*)d_in[8];
    const float* w_ih_l1  = (const float*)d_in[9];
    const float* w_hh_l1  = (const float*)d_in[10];
    const float* b_ih_l1  = (const float*)d_in[11];
    const float* b_hh_l1  = (const float*)d_in[12];
    const float* w_ih_l1r = (const float*)d_in[13];
    const float* b_ih_l1r = (const float*)d_in[15];
    const float* b_hh_l1r = (const float*)d_in[16];
    const float* fc_w     = (const float*)d_in[17];
    const float* fc_b     = (const float*)d_in[18];
    float* out = (float*)d_out;
    (void)in_sizes; (void)n_in; (void)out_size;

    float *xT, *xp0f, *xp0r, *h0c, *xp1f, *xp1r, *h1;
    cudaGetSymbolAddress((void**)&xT,   g_xT);
    cudaGetSymbolAddress((void**)&xp0f, g_xp0f);
    cudaGetSymbolAddress((void**)&xp0r, g_xp0r);
    cudaGetSymbolAddress((void**)&h0c,  g_h0c);
    cudaGetSymbolAddress((void**)&xp1f, g_xp1f);
    cudaGetSymbolAddress((void**)&xp1r, g_xp1r);
    cudaGetSymbolAddress((void**)&h1,   g_h1);

    cudaFuncSetAttribute((const void*)lstm_rec<4, 2>,
                         cudaFuncAttributeMaxDynamicSharedMemorySize, 65536);
    cudaFuncSetAttribute((const void*)lstm_rec<2, 1>,
                         cudaFuncAttributeMaxDynamicSharedMemorySize, 49152);

    // x -> xT [t][k][b]
    transpose_x<<<dim3(1024, 8), dim3(32, 8)>>>(x, xT);
    // layer-0 input projections (both directions) — TF32 tensor cores
    gemm_tf32<<<dim3(512, 2, 8), 256>>>(xT, w_ih_l0,  b_ih_l0,  b_hh_l0,  xp0f, 64, 1024);
    gemm_tf32<<<dim3(512, 2, 8), 256>>>(xT, w_ih_l0r, b_ih_l0r, b_hh_l0r, xp0r, 64, 1024);
    // layer-0 recurrence (fwd + rev concurrently)
    lstm_rec<4, 2><<<128, 256, 65536>>>(xp0f, xp0r, w_hh_l0, w_hh_l0r, h0c);
    // layer-1 fwd input projection (full) + rev projection at t=T-1 only
    gemm_tf32<<<dim3(512, 2, 8), 256>>>(h0c, w_ih_l1, b_ih_l1, b_hh_l1, xp1f, 512, 1024);
    gemm_tf32<<<dim3(1, 2, 8), 256>>>(h0c + (size_t)511 * 512 * 256,
                                      w_ih_l1r, b_ih_l1r, b_hh_l1r, xp1r, 512, 1024);
    // layer-1 fwd recurrence
    lstm_rec<2, 1><<<128, 256, 49152>>>(xp1f, xp1f, w_hh_l1, w_hh_l1, h1);
    // layer-1 rev single step + FC head
    finalize_kernel<<<256, 256>>>(xp1r, h1 + (size_t)511 * 256 * 256, fc_w, fc_b, out);
}

// round 4
// speedup vs baseline: 1.5118x; 1.3735x over previous
#include <cuda_runtime.h>
#include <cuda_bf16.h>
#include <cstdint>

// ---------------------------------------------------------------------------
// B=256, T=512, I=64, H=256, 2-layer bidirectional LSTM, FC on last timestep.
// R4: recurrent h@W_hh moved to TF32 tensor cores (3-term compensated),
//     partitioned 16-member group barriers, weights resident in smem.
// ---------------------------------------------------------------------------

__device__ float g_xT  [512 * 64 * 256];
__device__ float g_xp0f[512 * 1024 * 256];
__device__ float g_xp0r[512 * 1024 * 256];
__device__ float g_h0c [512 * 512 * 256];
__device__ float g_xp1f[512 * 1024 * 256];
__device__ float g_xp1r[1024 * 256];
__device__ float g_h1  [512 * 256 * 256];

__device__ unsigned g_gcnt[32 * 32];   // per-group, cacheline-strided
__device__ unsigned g_ggen[32 * 32];

__device__ __forceinline__ float sigm(float x) { return 1.0f / (1.0f + __expf(-x)); }

__device__ __forceinline__ uint32_t f2tf32(float x) {
    uint32_t r;
    asm("cvt.rna.tf32.f32 %0, %1;" : "=r"(r) : "f"(x));
    return r;
}

__device__ __forceinline__ void mma_tf32(float c[4], const uint32_t a[4], const uint32_t b[2]) {
    asm volatile(
        "mma.sync.aligned.m16n8k8.row.col.f32.tf32.tf32.f32 "
        "{%0,%1,%2,%3}, {%4,%5,%6,%7}, {%8,%9}, {%0,%1,%2,%3};"
        : "+f"(c[0]), "+f"(c[1]), "+f"(c[2]), "+f"(c[3])
        : "r"(a[0]), "r"(a[1]), "r"(a[2]), "r"(a[3]), "r"(b[0]), "r"(b[1]));
}

__device__ __forceinline__ void group_barrier(int grp, unsigned members) {
    __syncthreads();
    if (threadIdx.x == 0) {
        __threadfence();
        volatile unsigned* genp = (volatile unsigned*)&g_ggen[grp * 32];
        unsigned gen = *genp;
        if (atomicAdd(&g_gcnt[grp * 32], 1u) == members - 1) {
            atomicExch(&g_gcnt[grp * 32], 0u);
            __threadfence();
            atomicAdd(&g_ggen[grp * 32], 1u);
        } else {
            while (*genp == gen) __nanosleep(64);
        }
    }
    __syncthreads();
}

// ---------------------------------------------------------------------------
__global__ void transpose_x(const float* __restrict__ x, float* __restrict__ xT) {
    __shared__ float tile[32][33];
    int c0 = blockIdx.x * 32, r0 = blockIdx.y * 32;
    int tx = threadIdx.x, ty = threadIdx.y;
#pragma unroll
    for (int i = 0; i < 32; i += 8)
        tile[ty + i][tx] = x[(size_t)(r0 + ty + i) * 32768 + c0 + tx];
    __syncthreads();
#pragma unroll
    for (int i = 0; i < 32; i += 8)
        xT[(size_t)(c0 + ty + i) * 256 + r0 + tx] = tile[tx][ty + i];
}

// ---------------------------------------------------------------------------
// TF32 tensor-core GEMM (unchanged from R3).
// ---------------------------------------------------------------------------
#define WS_STRIDE 20
#define AS_STRIDE 132

__global__ void gemm_tf32(const float* __restrict__ A, const float* __restrict__ W,
                          const float* __restrict__ b1, const float* __restrict__ b2,
                          float* __restrict__ C, int K, int N) {
    __shared__ uint32_t Ws[128 * WS_STRIDE];
    __shared__ uint32_t As[16 * AS_STRIDE];

    int t  = blockIdx.x;
    int m0 = blockIdx.y * 128, n0 = blockIdx.z * 128;
    const float* At = A + (size_t)t * K * 256 + m0;
    const float* Wt = W + (size_t)n0 * K;
    float* Ct = C + (size_t)t * N * 256;

    int tid = threadIdx.x;
    int warp = tid >> 5, lane = tid & 31;
    int wn = (warp >> 2) * 64;
    int wb = (warp & 3) * 32;
    int lr = lane >> 2, lc = lane & 3;

    float acc[4][4][4];
#pragma unroll
    for (int i = 0; i < 4; i++)
#pragma unroll
        for (int jj = 0; jj < 4; jj++)
#pragma unroll
            for (int r = 0; r < 4; r++) acc[i][jj][r] = 0.0f;

    for (int k0 = 0; k0 < K; k0 += 16) {
#pragma unroll
        for (int q = 0; q < 2; q++) {
            int f = tid + 256 * q;
            int kk = f >> 5, b4 = (f & 31) * 4;
            float4 v = *(const float4*)&At[(size_t)(k0 + kk) * 256 + b4];
            uint4 u = make_uint4(f2tf32(v.x), f2tf32(v.y), f2tf32(v.z), f2tf32(v.w));
            *(uint4*)&As[kk * AS_STRIDE + b4] = u;
        }
#pragma unroll
        for (int q = 0; q < 2; q++) {
            int f = tid + 256 * q;
            int n = f >> 2, kq = (f & 3) * 4;
            float4 v = *(const float4*)&Wt[(size_t)n * K + k0 + kq];
            uint4 u = make_uint4(f2tf32(v.x), f2tf32(v.y), f2tf32(v.z), f2tf32(v.w));
            *(uint4*)&Ws[n * WS_STRIDE + kq] = u;
        }
        __syncthreads();

#pragma unroll
        for (int ks = 0; ks < 2; ks++) {
            int kk = ks * 8;
            uint32_t a[4][4], b[4][2];
#pragma unroll
            for (int ni = 0; ni < 4; ni++) {
                int n = wn + ni * 16 + lr;
                a[ni][0] = Ws[n * WS_STRIDE + kk + lc];
                a[ni][1] = Ws[(n + 8) * WS_STRIDE + kk + lc];
                a[ni][2] = Ws[n * WS_STRIDE + kk + lc + 4];
                a[ni][3] = Ws[(n + 8) * WS_STRIDE + kk + lc + 4];
            }
#pragma unroll
            for (int bi = 0; bi < 4; bi++) {
                int bb = wb + bi * 8 + lr;
                b[bi][0] = As[(kk + lc) * AS_STRIDE + bb];
                b[bi][1] = As[(kk + lc + 4) * AS_STRIDE + bb];
            }
#pragma unroll
            for (int ni = 0; ni < 4; ni++)
#pragma unroll
                for (int bi = 0; bi < 4; bi++)
                    mma_tf32(acc[ni][bi], a[ni], b[bi]);
        }
        __syncthreads();
    }

#pragma unroll
    for (int ni = 0; ni < 4; ni++) {
#pragma unroll
        for (int h = 0; h < 2; h++) {
            int n = n0 + wn + ni * 16 + lr + h * 8;
            float bias = b1[n] + b2[n];
#pragma unroll
            for (int bi = 0; bi < 4; bi++) {
                int bb = m0 + wb + bi * 8 + lc * 2;
                float2 v = make_float2(acc[ni][bi][h * 2] + bias,
                                       acc[ni][bi][h * 2 + 1] + bias);
                *(float2*)&Ct[(size_t)n * 256 + bb] = v;
            }
        }
    }
}

// ---------------------------------------------------------------------------
// Tensor-core persistent recurrence.
// CTA = (dir, ng in 0..15 => 16 units => 64 gate rows, bg in 0..3 => 64 batch).
// W_hh slice resident in smem (tf32 hi + bf16 lo) for all 512 steps.
// Per step: stage h_prev (hi+lo), 3-term compensated tf32 mma, gate update,
// 16-member group barrier over the CTAs sharing (dir, bg).
// ---------------------------------------------------------------------------
#define RWS 260   // Ws row stride (words)   mod32=4  -> conflict-free a-frags
#define RHS 72    // Hs row stride (words)   mod32=8  -> conflict-free b-frags
#define RGS 68    // gsh row stride (words)

template <int NDIR>
__global__ void lstm_rec_mma(const float* __restrict__ xp_f, const float* __restrict__ xp_r,
                             const float* __restrict__ whh_f, const float* __restrict__ whh_r,
                             float* __restrict__ hout) {
    constexpr int ROWS = 64, NG = 16, BGN = 4;
    constexpr int HOUT_ROWS = NDIR * 256;

    extern __shared__ char smraw[];
    uint32_t*      Ws  = (uint32_t*)smraw;                       // [64][260] tf32 hi
    __nv_bfloat16* Wl  = (__nv_bfloat16*)(Ws + ROWS * RWS);      // [64][260] lo
    uint32_t*      Hs  = (uint32_t*)(Wl + ROWS * RWS);           // [256][72] tf32 hi
    __nv_bfloat16* Hl  = (__nv_bfloat16*)(Hs + 256 * RHS);       // [256][72] lo
    float*         gsh = (float*)(Hl + 256 * RHS);               // [64][68]

    int tid = threadIdx.x;
    int bx  = blockIdx.x;
    int dir = (NDIR == 2) ? (bx / (NG * BGN)) : 0;
    int rem = bx % (NG * BGN);
    int ng = rem / BGN, bg = rem % BGN;
    int u0 = ng * 16, b0 = bg * 64;
    int grp = dir * BGN + bg;

    const float* xp  = dir ? xp_r : xp_f;
    const float* whh = dir ? whh_r : whh_f;

    // stage W_hh slice once: local row r = gate*16 + unit
    for (int i = tid; i < ROWS * 256; i += 256) {
        int r = i >> 8, k = i & 255;
        int grow = (r >> 4) * 256 + u0 + (r & 15);
        float w = whh[(size_t)grow * 256 + k];
        uint32_t hi = f2tf32(w);
        Ws[r * RWS + k] = hi;
        Wl[r * RWS + k] = __float2bfloat16(w - __uint_as_float(hi));
    }

    int warp = tid >> 5, lane = tid & 31;
    int nw = warp & 3, bw = warp >> 2;       // warp tile: 16 rows x 32 b
    int rbase = nw * 16, bbase = bw * 32;
    int lr = lane >> 2, lc = lane & 3;

    int uu = tid >> 4, bq = (tid & 15) * 4;  // update mapping: unit, 4 batches
    float cr0 = 0.f, cr1 = 0.f, cr2 = 0.f, cr3 = 0.f;

    __syncthreads();

    for (int s = 0; s < 512; s++) {
        int t = dir ? (511 - s) : s;

        // prefetch xp gates for this thread's (unit, 4 batches)
        const float* xpt = xp + (size_t)t * 1024 * 256;
        float4 xv[4];
#pragma unroll
        for (int g = 0; g < 4; g++)
            xv[g] = *(const float4*)&xpt[(size_t)(g * 256 + u0 + uu) * 256 + b0 + bq];

        float acc[4][4];
#pragma unroll
        for (int bi = 0; bi < 4; bi++)
#pragma unroll
            for (int r = 0; r < 4; r++) acc[bi][r] = 0.0f;

        if (s > 0) {
            int tp = dir ? (t + 1) : (t - 1);
            const float* hprev = hout + ((size_t)tp * HOUT_ROWS + dir * 256) * 256;
            // stage h_prev[256][b0..b0+64) as tf32 hi + bf16 lo
            for (int i = tid; i < 256 * 16; i += 256) {
                int r = i >> 4, q = (i & 15) * 4;
                float4 v = *(const float4*)&hprev[(size_t)r * 256 + b0 + q];
                uint32_t h0 = f2tf32(v.x), h1 = f2tf32(v.y);
                uint32_t h2 = f2tf32(v.z), h3 = f2tf32(v.w);
                *(uint4*)&Hs[r * RHS + q] = make_uint4(h0, h1, h2, h3);
                __nv_bfloat16* hl = &Hl[r * RHS + q];
                hl[0] = __float2bfloat16(v.x - __uint_as_float(h0));
                hl[1] = __float2bfloat16(v.y - __uint_as_float(h1));
                hl[2] = __float2bfloat16(v.z - __uint_as_float(h2));
                hl[3] = __float2bfloat16(v.w - __uint_as_float(h3));
            }
            __syncthreads();

#pragma unroll 2
            for (int kk = 0; kk < 256; kk += 8) {
                uint32_t a[4], al[4];
                const uint32_t* w0p = &Ws[(rbase + lr) * RWS + kk + lc];
                const uint32_t* w1p = &Ws[(rbase + lr + 8) * RWS + kk + lc];
                a[0] = w0p[0]; a[2] = w0p[4];
                a[1] = w1p[0]; a[3] = w1p[4];
                const __nv_bfloat16* l0p = &Wl[(rbase + lr) * RWS + kk + lc];
                const __nv_bfloat16* l1p = &Wl[(rbase + lr + 8) * RWS + kk + lc];
                al[0] = __float_as_uint(__bfloat162float(l0p[0]));
                al[2] = __float_as_uint(__bfloat162float(l0p[4]));
                al[1] = __float_as_uint(__bfloat162float(l1p[0]));
                al[3] = __float_as_uint(__bfloat162float(l1p[4]));
#pragma unroll
                for (int bi = 0; bi < 4; bi++) {
                    int bcol = bbase + bi * 8 + lr;
                    uint32_t b[2], bl[2];
                    b[0] = Hs[(kk + lc) * RHS + bcol];
                    b[1] = Hs[(kk + lc + 4) * RHS + bcol];
                    bl[0] = __float_as_uint(__bfloat162float(Hl[(kk + lc) * RHS + bcol]));
                    bl[1] = __float_as_uint(__bfloat162float(Hl[(kk + lc + 4) * RHS + bcol]));
                    mma_tf32(acc[bi], a,  b);    // hi*hi
                    mma_tf32(acc[bi], a,  bl);   // hi*lo
                    mma_tf32(acc[bi], al, b);    // lo*hi
                }
            }
        }

        // gates -> gsh
#pragma unroll
        for (int bi = 0; bi < 4; bi++) {
            int col = bbase + bi * 8 + lc * 2;
            *(float2*)&gsh[(rbase + lr) * RGS + col]     = make_float2(acc[bi][0], acc[bi][1]);
            *(float2*)&gsh[(rbase + lr + 8) * RGS + col] = make_float2(acc[bi][2], acc[bi][3]);
        }
        __syncthreads();

        // LSTM update: thread owns (unit uu, batches bq..bq+3)
        float4 gv[4];
#pragma unroll
        for (int g = 0; g < 4; g++) {
            float4 mv = *(const float4*)&gsh[(g * 16 + uu) * RGS + bq];
            gv[g] = make_float4(xv[g].x + mv.x, xv[g].y + mv.y,
                                xv[g].z + mv.z, xv[g].w + mv.w);
        }
        cr0 = sigm(gv[1].x) * cr0 + sigm(gv[0].x) * tanhf(gv[2].x);
        cr1 = sigm(gv[1].y) * cr1 + sigm(gv[0].y) * tanhf(gv[2].y);
        cr2 = sigm(gv[1].z) * cr2 + sigm(gv[0].z) * tanhf(gv[2].z);
        cr3 = sigm(gv[1].w) * cr3 + sigm(gv[0].w) * tanhf(gv[2].w);
        float4 hv = make_float4(sigm(gv[3].x) * tanhf(cr0),
                                sigm(gv[3].y) * tanhf(cr1),
                                sigm(gv[3].z) * tanhf(cr2),
                                sigm(gv[3].w) * tanhf(cr3));
        *(float4*)&hout[((size_t)t * HOUT_ROWS + dir * 256 + u0 + uu) * 256 + b0 + bq] = hv;

        group_barrier(grp, NG);
    }
}

// ---------------------------------------------------------------------------
__global__ void finalize_kernel(const float* __restrict__ xp1r,
                                const float* __restrict__ h1last,
                                const float* __restrict__ fc_w,
                                const float* __restrict__ fc_b,
                                float* __restrict__ out) {
    int b = blockIdx.x, u = threadIdx.x;
    float ig = xp1r[(size_t)(0   + u) * 256 + b];
    float gg = xp1r[(size_t)(512 + u) * 256 + b];
    float og = xp1r[(size_t)(768 + u) * 256 + b];
    float cc = sigm(ig) * tanhf(gg);
    float hr = sigm(og) * tanhf(cc);
    float p = fc_w[u] * h1last[(size_t)u * 256 + b] + fc_w[256 + u] * hr;
    __shared__ float red[256];
    red[u] = p;
    __syncthreads();
    for (int off = 128; off > 0; off >>= 1) {
        if (u < off) red[u] += red[u + off];
        __syncthreads();
    }
    if (u == 0) out[b] = red[0] + fc_b[0];
}

// ---------------------------------------------------------------------------
extern "C" void kernel_launch(void* const* d_in, const int* in_sizes, int n_in,
                              void* d_out, int out_size) {
    const float* x        = (const float*)d_in[0];
    const float* w_ih_l0  = (const float*)d_in[1];
    const float* w_hh_l0  = (const float*)d_in[2];
    const float* b_ih_l0  = (const float*)d_in[3];
    const float* b_hh_l0  = (const float*)d_in[4];
    const float* w_ih_l0r = (const float*)d_in[5];
    const float* w_hh_l0r = (const float*)d_in[6];
    const float* b_ih_l0r = (const float*)d_in[7];
    const float* b_hh_l0r = (const float*)d_in[8];
    const float* w_ih_l1  = (const float*)d_in[9];
    const float* w_hh_l1  = (const float*)d_in[10];
    const float* b_ih_l1  = (const float*)d_in[11];
    const float* b_hh_l1  = (const float*)d_in[12];
    const float* w_ih_l1r = (const float*)d_in[13];
    const float* b_ih_l1r = (const float*)d_in[15];
    const float* b_hh_l1r = (const float*)d_in[16];
    const float* fc_w     = (const float*)d_in[17];
    const float* fc_b     = (const float*)d_in[18];
    float* out = (float*)d_out;
    (void)in_sizes; (void)n_in; (void)out_size;

    float *xT, *xp0f, *xp0r, *h0c, *xp1f, *xp1r, *h1;
    cudaGetSymbolAddress((void**)&xT,   g_xT);
    cudaGetSymbolAddress((void**)&xp0f, g_xp0f);
    cudaGetSymbolAddress((void**)&xp0r, g_xp0r);
    cudaGetSymbolAddress((void**)&h0c,  g_h0c);
    cudaGetSymbolAddress((void**)&xp1f, g_xp1f);
    cudaGetSymbolAddress((void**)&xp1r, g_xp1r);
    cudaGetSymbolAddress((void**)&h1,   g_h1);

    const int REC_SMEM = 227840;  // Ws+Wl+Hs+Hl+gsh
    cudaFuncSetAttribute((const void*)lstm_rec_mma<2>,
                         cudaFuncAttributeMaxDynamicSharedMemorySize, REC_SMEM);
    cudaFuncSetAttribute((const void*)lstm_rec_mma<1>,
                         cudaFuncAttributeMaxDynamicSharedMemorySize, REC_SMEM);

    transpose_x<<<dim3(1024, 8), dim3(32, 8)>>>(x, xT);
    gemm_tf32<<<dim3(512, 2, 8), 256>>>(xT, w_ih_l0,  b_ih_l0,  b_hh_l0,  xp0f, 64, 1024);
    gemm_tf32<<<dim3(512, 2, 8), 256>>>(xT, w_ih_l0r, b_ih_l0r, b_hh_l0r, xp0r, 64, 1024);
    lstm_rec_mma<2><<<128, 256, REC_SMEM>>>(xp0f, xp0r, w_hh_l0, w_hh_l0r, h0c);
    gemm_tf32<<<dim3(512, 2, 8), 256>>>(h0c, w_ih_l1, b_ih_l1, b_hh_l1, xp1f, 512, 1024);
    gemm_tf32<<<dim3(1, 2, 8), 256>>>(h0c + (size_t)511 * 512 * 256,
                                      w_ih_l1r, b_ih_l1r, b_hh_l1r, xp1r, 512, 1024);
    lstm_rec_mma<1><<<64, 256, REC_SMEM>>>(xp1f, xp1f, w_hh_l1, w_hh_l1, h1);
    finalize_kernel<<<256, 256>>>(xp1r, h1 + (size_t)511 * 256 * 256, fc_w, fc_b, out);
}

// round 5
// speedup vs baseline: 2.2916x; 1.5158x over previous
#include <cuda_runtime.h>
#include <cuda_bf16.h>
#include <cstdint>

// ---------------------------------------------------------------------------
// B=256, T=512, I=64, H=256, 2-layer bidirectional LSTM, FC on last timestep.
// R5: recurrence on bf16 m16n8k16 tensor cores, 3-term hi/lo compensation,
//     512 threads/CTA, pre-packed bf16x2 fragments (no inner-loop converts).
// ---------------------------------------------------------------------------

__device__ float g_xT  [512 * 64 * 256];
__device__ float g_xp0f[512 * 1024 * 256];
__device__ float g_xp0r[512 * 1024 * 256];
__device__ float g_h0c [512 * 512 * 256];
__device__ float g_xp1f[512 * 1024 * 256];
__device__ float g_xp1r[1024 * 256];
__device__ float g_h1  [512 * 256 * 256];

__device__ unsigned g_gcnt[32 * 32];
__device__ unsigned g_ggen[32 * 32];

__device__ __forceinline__ float sigm(float x) { return 1.0f / (1.0f + __expf(-x)); }

__device__ __forceinline__ uint32_t f2tf32(float x) {
    uint32_t r;
    asm("cvt.rna.tf32.f32 %0, %1;" : "=r"(r) : "f"(x));
    return r;
}

__device__ __forceinline__ void mma_tf32(float c[4], const uint32_t a[4], const uint32_t b[2]) {
    asm volatile(
        "mma.sync.aligned.m16n8k8.row.col.f32.tf32.tf32.f32 "
        "{%0,%1,%2,%3}, {%4,%5,%6,%7}, {%8,%9}, {%0,%1,%2,%3};"
        : "+f"(c[0]), "+f"(c[1]), "+f"(c[2]), "+f"(c[3])
        : "r"(a[0]), "r"(a[1]), "r"(a[2]), "r"(a[3]), "r"(b[0]), "r"(b[1]));
}

__device__ __forceinline__ void mma_bf16(float c[4], const uint32_t a[4], const uint32_t b[2]) {
    asm volatile(
        "mma.sync.aligned.m16n8k16.row.col.f32.bf16.bf16.f32 "
        "{%0,%1,%2,%3}, {%4,%5,%6,%7}, {%8,%9}, {%0,%1,%2,%3};"
        : "+f"(c[0]), "+f"(c[1]), "+f"(c[2]), "+f"(c[3])
        : "r"(a[0]), "r"(a[1]), "r"(a[2]), "r"(a[3]), "r"(b[0]), "r"(b[1]));
}

__device__ __forceinline__ void group_barrier(int grp, unsigned members) {
    __syncthreads();
    if (threadIdx.x == 0) {
        __threadfence();
        volatile unsigned* genp = (volatile unsigned*)&g_ggen[grp * 32];
        unsigned gen = *genp;
        if (atomicAdd(&g_gcnt[grp * 32], 1u) == members - 1) {
            atomicExch(&g_gcnt[grp * 32], 0u);
            __threadfence();
            atomicAdd(&g_ggen[grp * 32], 1u);
        } else {
            while (*genp == gen) __nanosleep(64);
        }
    }
    __syncthreads();
}

// ---------------------------------------------------------------------------
__global__ void transpose_x(const float* __restrict__ x, float* __restrict__ xT) {
    __shared__ float tile[32][33];
    int c0 = blockIdx.x * 32, r0 = blockIdx.y * 32;
    int tx = threadIdx.x, ty = threadIdx.y;
#pragma unroll
    for (int i = 0; i < 32; i += 8)
        tile[ty + i][tx] = x[(size_t)(r0 + ty + i) * 32768 + c0 + tx];
    __syncthreads();
#pragma unroll
    for (int i = 0; i < 32; i += 8)
        xT[(size_t)(c0 + ty + i) * 256 + r0 + tx] = tile[tx][ty + i];
}

// ---------------------------------------------------------------------------
// TF32 tensor-core GEMM for input projections (unchanged).
// ---------------------------------------------------------------------------
#define WS_STRIDE 20
#define AS_STRIDE 132

__global__ void gemm_tf32(const float* __restrict__ A, const float* __restrict__ W,
                          const float* __restrict__ b1, const float* __restrict__ b2,
                          float* __restrict__ C, int K, int N) {
    __shared__ uint32_t Ws[128 * WS_STRIDE];
    __shared__ uint32_t As[16 * AS_STRIDE];

    int t  = blockIdx.x;
    int m0 = blockIdx.y * 128, n0 = blockIdx.z * 128;
    const float* At = A + (size_t)t * K * 256 + m0;
    const float* Wt = W + (size_t)n0 * K;
    float* Ct = C + (size_t)t * N * 256;

    int tid = threadIdx.x;
    int warp = tid >> 5, lane = tid & 31;
    int wn = (warp >> 2) * 64;
    int wb = (warp & 3) * 32;
    int lr = lane >> 2, lc = lane & 3;

    float acc[4][4][4];
#pragma unroll
    for (int i = 0; i < 4; i++)
#pragma unroll
        for (int jj = 0; jj < 4; jj++)
#pragma unroll
            for (int r = 0; r < 4; r++) acc[i][jj][r] = 0.0f;

    for (int k0 = 0; k0 < K; k0 += 16) {
#pragma unroll
        for (int q = 0; q < 2; q++) {
            int f = tid + 256 * q;
            int kk = f >> 5, b4 = (f & 31) * 4;
            float4 v = *(const float4*)&At[(size_t)(k0 + kk) * 256 + b4];
            uint4 u = make_uint4(f2tf32(v.x), f2tf32(v.y), f2tf32(v.z), f2tf32(v.w));
            *(uint4*)&As[kk * AS_STRIDE + b4] = u;
        }
#pragma unroll
        for (int q = 0; q < 2; q++) {
            int f = tid + 256 * q;
            int n = f >> 2, kq = (f & 3) * 4;
            float4 v = *(const float4*)&Wt[(size_t)n * K + k0 + kq];
            uint4 u = make_uint4(f2tf32(v.x), f2tf32(v.y), f2tf32(v.z), f2tf32(v.w));
            *(uint4*)&Ws[n * WS_STRIDE + kq] = u;
        }
        __syncthreads();

#pragma unroll
        for (int ks = 0; ks < 2; ks++) {
            int kk = ks * 8;
            uint32_t a[4][4], b[4][2];
#pragma unroll
            for (int ni = 0; ni < 4; ni++) {
                int n = wn + ni * 16 + lr;
                a[ni][0] = Ws[n * WS_STRIDE + kk + lc];
                a[ni][1] = Ws[(n + 8) * WS_STRIDE + kk + lc];
                a[ni][2] = Ws[n * WS_STRIDE + kk + lc + 4];
                a[ni][3] = Ws[(n + 8) * WS_STRIDE + kk + lc + 4];
            }
#pragma unroll
            for (int bi = 0; bi < 4; bi++) {
                int bb = wb + bi * 8 + lr;
                b[bi][0] = As[(kk + lc) * AS_STRIDE + bb];
                b[bi][1] = As[(kk + lc + 4) * AS_STRIDE + bb];
            }
#pragma unroll
            for (int ni = 0; ni < 4; ni++)
#pragma unroll
                for (int bi = 0; bi < 4; bi++)
                    mma_tf32(acc[ni][bi], a[ni], b[bi]);
        }
        __syncthreads();
    }

#pragma unroll
    for (int ni = 0; ni < 4; ni++) {
#pragma unroll
        for (int h = 0; h < 2; h++) {
            int n = n0 + wn + ni * 16 + lr + h * 8;
            float bias = b1[n] + b2[n];
#pragma unroll
            for (int bi = 0; bi < 4; bi++) {
                int bb = m0 + wb + bi * 8 + lc * 2;
                float2 v = make_float2(acc[ni][bi][h * 2] + bias,
                                       acc[ni][bi][h * 2 + 1] + bias);
                *(float2*)&Ct[(size_t)n * 256 + bb] = v;
            }
        }
    }
}

// ---------------------------------------------------------------------------
// bf16 tensor-core persistent recurrence, 512 threads/CTA.
// CTA = (dir, 16 units -> 64 gate rows, 64-batch slice).
// W_hh resident in smem as bf16x2 hi/lo pairs (k-packed) for all 512 steps.
// Per step: stage h_prev as bf16x2 hi/lo, 3-term mma, gate update,
// 16-member group barrier over CTAs sharing (dir, batch-slice).
// ---------------------------------------------------------------------------
#define WS2 132   // W2 row stride (words over 128 k-pairs)  mod32=4
#define HS2 72    // H2 row stride (words over 64 batch)     mod32=8
#define RGS 72    // gsh row stride

__device__ __forceinline__ uint32_t packbf2(float a, float b) {
    __nv_bfloat162 t = __floats2bfloat162_rn(a, b);
    return *(uint32_t*)&t;
}

template <int NDIR>
__global__ void __launch_bounds__(512, 1)
lstm_rec_mma(const float* __restrict__ xp_f, const float* __restrict__ xp_r,
             const float* __restrict__ whh_f, const float* __restrict__ whh_r,
             float* __restrict__ hout) {
    constexpr int NG = 16, BGN = 4;
    constexpr int HOUT_ROWS = NDIR * 256;

    extern __shared__ char smraw[];
    uint32_t* W2hi = (uint32_t*)smraw;                 // [64][132]
    uint32_t* W2lo = W2hi + 64 * WS2;                  // [64][132]
    uint32_t* H2hi = W2lo + 64 * WS2;                  // [128][72]
    uint32_t* H2lo = H2hi + 128 * HS2;                 // [128][72]
    float*    gsh  = (float*)(H2lo + 128 * HS2);       // [64][72]

    int tid = threadIdx.x;
    int bx  = blockIdx.x;
    int dir = (NDIR == 2) ? (bx / (NG * BGN)) : 0;
    int rem = bx % (NG * BGN);
    int ng = rem / BGN, bg = rem % BGN;
    int u0 = ng * 16, b0 = bg * 64;
    int grp = dir * BGN + bg;

    const float* xp  = dir ? xp_r : xp_f;
    const float* whh = dir ? whh_r : whh_f;

    // stage W_hh slice once: local row r = gate*16 + unit, k packed in pairs
    for (int i = tid; i < 64 * 128; i += 512) {
        int r = i >> 7, kp = i & 127;
        int grow = (r >> 4) * 256 + u0 + (r & 15);
        float2 w = *(const float2*)&whh[(size_t)grow * 256 + 2 * kp];
        uint32_t hi = packbf2(w.x, w.y);
        __nv_bfloat162 hb = *(__nv_bfloat162*)&hi;
        W2hi[r * WS2 + kp] = hi;
        W2lo[r * WS2 + kp] = packbf2(w.x - __low2float(hb), w.y - __high2float(hb));
    }

    int warp = tid >> 5, lane = tid & 31;
    int rbase = (warp & 3) * 16;        // gate-row tile
    int bbase = (warp >> 2) * 16;       // batch tile
    int lr = lane >> 2, lc = lane & 3;

    int uu = tid >> 5;                  // owned unit (0..15)
    int bq = (lane) * 2;                // owned batch pair
    float cr0 = 0.f, cr1 = 0.f;

    __syncthreads();

    for (int s = 0; s < 512; s++) {
        int t = dir ? (511 - s) : s;

        // prefetch xp gates for (unit uu, batches bq..bq+1)
        const float* xpt = xp + (size_t)t * 1024 * 256;
        float2 xv[4];
#pragma unroll
        for (int g = 0; g < 4; g++)
            xv[g] = *(const float2*)&xpt[(size_t)(g * 256 + u0 + uu) * 256 + b0 + bq];

        float acc[2][4];
#pragma unroll
        for (int bi = 0; bi < 2; bi++)
#pragma unroll
            for (int r = 0; r < 4; r++) acc[bi][r] = 0.0f;

        if (s > 0) {
            int tp = dir ? (t + 1) : (t - 1);
            const float* hprev = hout + ((size_t)tp * HOUT_ROWS + dir * 256) * 256;
            // stage h_prev[256][b0..b0+64) as bf16x2 hi/lo, k packed in pairs
            for (int i = tid; i < 128 * 16; i += 512) {
                int kp = i >> 4, q = (i & 15) * 4;
                const float* r0p = &hprev[(size_t)(2 * kp) * 256 + b0 + q];
                float4 va = *(const float4*)r0p;
                float4 vb = *(const float4*)(r0p + 256);
                uint32_t h0 = packbf2(va.x, vb.x), h1 = packbf2(va.y, vb.y);
                uint32_t h2 = packbf2(va.z, vb.z), h3 = packbf2(va.w, vb.w);
                *(uint4*)&H2hi[kp * HS2 + q] = make_uint4(h0, h1, h2, h3);
                __nv_bfloat162 p0 = *(__nv_bfloat162*)&h0, p1 = *(__nv_bfloat162*)&h1;
                __nv_bfloat162 p2 = *(__nv_bfloat162*)&h2, p3 = *(__nv_bfloat162*)&h3;
                uint32_t l0 = packbf2(va.x - __low2float(p0), vb.x - __high2float(p0));
                uint32_t l1 = packbf2(va.y - __low2float(p1), vb.y - __high2float(p1));
                uint32_t l2 = packbf2(va.z - __low2float(p2), vb.z - __high2float(p2));
                uint32_t l3 = packbf2(va.w - __low2float(p3), vb.w - __high2float(p3));
                *(uint4*)&H2lo[kp * HS2 + q] = make_uint4(l0, l1, l2, l3);
            }
            __syncthreads();

#pragma unroll 4
            for (int ch = 0; ch < 16; ch++) {
                int kk2 = ch * 8;
                uint32_t ahi[4], alo[4];
                int ra = (rbase + lr) * WS2 + kk2 + lc;
                ahi[0] = W2hi[ra];            ahi[2] = W2hi[ra + 4];
                ahi[1] = W2hi[ra + 8 * WS2];  ahi[3] = W2hi[ra + 8 * WS2 + 4];
                alo[0] = W2lo[ra];            alo[2] = W2lo[ra + 4];
                alo[1] = W2lo[ra + 8 * WS2];  alo[3] = W2lo[ra + 8 * WS2 + 4];
#pragma unroll
                for (int bi = 0; bi < 2; bi++) {
                    int bcol = bbase + bi * 8 + lr;
                    uint32_t bhi[2], blo[2];
                    bhi[0] = H2hi[(kk2 + lc) * HS2 + bcol];
                    bhi[1] = H2hi[(kk2 + lc + 4) * HS2 + bcol];
                    blo[0] = H2lo[(kk2 + lc) * HS2 + bcol];
                    blo[1] = H2lo[(kk2 + lc + 4) * HS2 + bcol];
                    mma_bf16(acc[bi], ahi, bhi);
                    mma_bf16(acc[bi], ahi, blo);
                    mma_bf16(acc[bi], alo, bhi);
                }
            }
        }

        // gates -> gsh
#pragma unroll
        for (int bi = 0; bi < 2; bi++) {
            int col = bbase + bi * 8 + lc * 2;
            *(float2*)&gsh[(rbase + lr) * RGS + col]     = make_float2(acc[bi][0], acc[bi][1]);
            *(float2*)&gsh[(rbase + lr + 8) * RGS + col] = make_float2(acc[bi][2], acc[bi][3]);
        }
        __syncthreads();

        // LSTM update: thread owns (unit uu, batches bq, bq+1)
        float2 gv[4];
#pragma unroll
        for (int g = 0; g < 4; g++) {
            float2 mv = *(const float2*)&gsh[(g * 16 + uu) * RGS + bq];
            gv[g] = make_float2(xv[g].x + mv.x, xv[g].y + mv.y);
        }
        cr0 = sigm(gv[1].x) * cr0 + sigm(gv[0].x) * tanhf(gv[2].x);
        cr1 = sigm(gv[1].y) * cr1 + sigm(gv[0].y) * tanhf(gv[2].y);
        float2 hv = make_float2(sigm(gv[3].x) * tanhf(cr0),
                                sigm(gv[3].y) * tanhf(cr1));
        *(float2*)&hout[((size_t)t * HOUT_ROWS + dir * 256 + u0 + uu) * 256 + b0 + bq] = hv;

        group_barrier(grp, NG);
    }
}

// ---------------------------------------------------------------------------
__global__ void finalize_kernel(const float* __restrict__ xp1r,
                                const float* __restrict__ h1last,
                                const float* __restrict__ fc_w,
                                const float* __restrict__ fc_b,
                                float* __restrict__ out) {
    int b = blockIdx.x, u = threadIdx.x;
    float ig = xp1r[(size_t)(0   + u) * 256 + b];
    float gg = xp1r[(size_t)(512 + u) * 256 + b];
    float og = xp1r[(size_t)(768 + u) * 256 + b];
    float cc = sigm(ig) * tanhf(gg);
    float hr = sigm(og) * tanhf(cc);
    float p = fc_w[u] * h1last[(size_t)u * 256 + b] + fc_w[256 + u] * hr;
    __shared__ float red[256];
    red[u] = p;
    __syncthreads();
    for (int off = 128; off > 0; off >>= 1) {
        if (u < off) red[u] += red[u + off];
        __syncthreads();
    }
    if (u == 0) out[b] = red[0] + fc_b[0];
}

// ---------------------------------------------------------------------------
extern "C" void kernel_launch(void* const* d_in, const int* in_sizes, int n_in,
                              void* d_out, int out_size) {
    const float* x        = (const float*)d_in[0];
    const float* w_ih_l0  = (const float*)d_in[1];
    const float* w_hh_l0  = (const float*)d_in[2];
    const float* b_ih_l0  = (const float*)d_in[3];
    const float* b_hh_l0  = (const float*)d_in[4];
    const float* w_ih_l0r = (const float*)d_in[5];
    const float* w_hh_l0r = (const float*)d_in[6];
    const float* b_ih_l0r = (const float*)d_in[7];
    const float* b_hh_l0r = (const float*)d_in[8];
    const float* w_ih_l1  = (const float*)d_in[9];
    const float* w_hh_l1  = (const float*)d_in[10];
    const float* b_ih_l1  = (const float*)d_in[11];
    const float* b_hh_l1  = (const float*)d_in[12];
    const float* w_ih_l1r = (const float*)d_in[13];
    const float* b_ih_l1r = (const float*)d_in[15];
    const float* b_hh_l1r = (const float*)d_in[16];
    const float* fc_w     = (const float*)d_in[17];
    const float* fc_b     = (const float*)d_in[18];
    float* out = (float*)d_out;
    (void)in_sizes; (void)n_in; (void)out_size;

    float *xT, *xp0f, *xp0r, *h0c, *xp1f, *xp1r, *h1;
    cudaGetSymbolAddress((void**)&xT,   g_xT);
    cudaGetSymbolAddress((void**)&xp0f, g_xp0f);
    cudaGetSymbolAddress((void**)&xp0r, g_xp0r);
    cudaGetSymbolAddress((void**)&h0c,  g_h0c);
    cudaGetSymbolAddress((void**)&xp1f, g_xp1f);
    cudaGetSymbolAddress((void**)&xp1r, g_xp1r);
    cudaGetSymbolAddress((void**)&h1,   g_h1);

    const int REC_SMEM = (64 * WS2 * 2 + 128 * HS2 * 2 + 64 * RGS) * 4;  // 159744
    cudaFuncSetAttribute((const void*)lstm_rec_mma<2>,
                         cudaFuncAttributeMaxDynamicSharedMemorySize, REC_SMEM);
    cudaFuncSetAttribute((const void*)lstm_rec_mma<1>,
                         cudaFuncAttributeMaxDynamicSharedMemorySize, REC_SMEM);

    transpose_x<<<dim3(1024, 8), dim3(32, 8)>>>(x, xT);
    gemm_tf32<<<dim3(512, 2, 8), 256>>>(xT, w_ih_l0,  b_ih_l0,  b_hh_l0,  xp0f, 64, 1024);
    gemm_tf32<<<dim3(512, 2, 8), 256>>>(xT, w_ih_l0r, b_ih_l0r, b_hh_l0r, xp0r, 64, 1024);
    lstm_rec_mma<2><<<128, 512, REC_SMEM>>>(xp0f, xp0r, w_hh_l0, w_hh_l0r, h0c);
    gemm_tf32<<<dim3(512, 2, 8), 256>>>(h0c, w_ih_l1, b_ih_l1, b_hh_l1, xp1f, 512, 1024);
    gemm_tf32<<<dim3(1, 2, 8), 256>>>(h0c + (size_t)511 * 512 * 256,
                                      w_ih_l1r, b_ih_l1r, b_hh_l1r, xp1r, 512, 1024);
    lstm_rec_mma<1><<<64, 512, REC_SMEM>>>(xp1f, xp1f, w_hh_l1, w_hh_l1, h1);
    finalize_kernel<<<256, 256>>>(xp1r, h1 + (size_t)511 * 256 * 256, fc_w, fc_b, out);
}